// round 2
// baseline (speedup 1.0000x reference)
#include <cuda_runtime.h>

// QuantizedCodebook (VQ-VAE quantize): N=131072 rows of D=64, K=512 codes.
// out layout assumed: [loss(1) | quantize(N*D) | indices(N)] all fp32.
// NOTE: out+1 is only 4B-aligned -> quantize must be written with 32-bit stores.

#define KCODES 512
#define DDIM   64
#define TPB    256

__device__ double g_loss_sum;

__device__ __forceinline__ unsigned long long f32x2_dup(float v) {
    unsigned long long r;
    asm("mov.b64 %0, {%1, %1};" : "=l"(r) : "f"(v));
    return r;
}
__device__ __forceinline__ unsigned long long ffma2(unsigned long long a,
                                                    unsigned long long b,
                                                    unsigned long long c) {
    unsigned long long d;
    asm("fma.rn.f32x2 %0, %1, %2, %3;" : "=l"(d) : "l"(a), "l"(b), "l"(c));
    return d;
}
__device__ __forceinline__ float2 as_float2(unsigned long long a) {
    float2 f;
    asm("mov.b64 {%0, %1}, %2;" : "=f"(f.x), "=f"(f.y) : "l"(a));
    return f;
}

__global__ void vq_zero_kernel() { g_loss_sum = 0.0; }

__global__ void vq_finalize_kernel(float* out_loss, int total_elems) {
    // loss = encoding_loss + 0.25*commit_loss, both numerically mean((q~-x)^2)
    out_loss[0] = (float)(g_loss_sum * 1.25 / (double)total_elems);
}

__global__ void __launch_bounds__(TPB, 1)
vq_main_kernel(const float* __restrict__ x, const float* __restrict__ cb,
               float* __restrict__ out_q, float* __restrict__ out_idx, int nrows)
{
    extern __shared__ float smem[];
    float* spair = smem;                 // KCODES*DDIM floats, pair-interleaved
    float* scq   = smem + KCODES * DDIM; // KCODES floats: ||c_j||^2

    const int tid = threadIdx.x;

    // Cooperative load of codebook into smem, interleaving code pairs:
    // spair[pair*128 + 2*i + parity] = cb[(2*pair+parity)*64 + i]
    for (int idx = tid; idx < KCODES * DDIM; idx += TPB) {
        int j = idx / DDIM;
        int i = idx - j * DDIM;
        spair[(j >> 1) * (2 * DDIM) + (i << 1) + (j & 1)] = cb[idx];
    }
    // ||c_j||^2
    for (int j = tid; j < KCODES; j += TPB) {
        const float* c = cb + j * DDIM;
        float s = 0.f;
        #pragma unroll
        for (int i = 0; i < DDIM; i++) s = fmaf(c[i], c[i], s);
        scq[j] = s;
    }
    __syncthreads();

    // Persistent: block owns contiguous row range.
    const int nb    = gridDim.x;
    const int start = (int)(((long long)blockIdx.x * nrows) / nb);
    const int end   = (int)(((long long)(blockIdx.x + 1) * nrows) / nb);

    float lsum = 0.f;

    for (int r = start + tid; r < end; r += TPB) {
        // Load row, duplicated into f32x2 lanes: xd[i] = {x_i, x_i}
        const float4* xr = reinterpret_cast<const float4*>(x + (size_t)r * DDIM);
        unsigned long long xd[DDIM];
        #pragma unroll
        for (int i = 0; i < DDIM / 4; i++) {
            float4 v = xr[i];
            xd[4 * i + 0] = f32x2_dup(v.x);
            xd[4 * i + 1] = f32x2_dup(v.y);
            xd[4 * i + 2] = f32x2_dup(v.z);
            xd[4 * i + 3] = f32x2_dup(v.w);
        }

        float best = 3.402823466e38f;
        int   bidx = 0;

        // 4 codes per outer iteration: two f32x2 dot-product chains.
        #pragma unroll 1
        for (int jp = 0; jp < KCODES / 2; jp += 2) {
            const ulonglong2* p0 =
                reinterpret_cast<const ulonglong2*>(spair + jp * (2 * DDIM));
            const ulonglong2* p1 =
                reinterpret_cast<const ulonglong2*>(spair + (jp + 1) * (2 * DDIM));
            unsigned long long a0 = 0ull, a1 = 0ull;
            #pragma unroll
            for (int i = 0; i < DDIM / 2; i++) {
                ulonglong2 c0 = p0[i];   // {pack(e_i,o_i), pack(e_{i+1},o_{i+1})}
                ulonglong2 c1 = p1[i];
                a0 = ffma2(xd[2 * i],     c0.x, a0);
                a0 = ffma2(xd[2 * i + 1], c0.y, a0);
                a1 = ffma2(xd[2 * i],     c1.x, a1);
                a1 = ffma2(xd[2 * i + 1], c1.y, a1);
            }
            float2 d0 = as_float2(a0);   // dots for codes 2jp, 2jp+1
            float2 d1 = as_float2(a1);   // dots for codes 2jp+2, 2jp+3
            float s0 = fmaf(-2.f, d0.x, scq[2 * jp + 0]);
            float s1 = fmaf(-2.f, d0.y, scq[2 * jp + 1]);
            float s2 = fmaf(-2.f, d1.x, scq[2 * jp + 2]);
            float s3 = fmaf(-2.f, d1.y, scq[2 * jp + 3]);
            // strict < in ascending code order -> first-min like jnp.argmin
            if (s0 < best) { best = s0; bidx = 2 * jp + 0; }
            if (s1 < best) { best = s1; bidx = 2 * jp + 1; }
            if (s2 < best) { best = s2; bidx = 2 * jp + 2; }
            if (s3 < best) { best = s3; bidx = 2 * jp + 3; }
        }

        // Epilogue: index, quantize = x + (c - x)  (matches STE rounding), loss.
        out_idx[r] = (float)bidx;
        const float4* crow = reinterpret_cast<const float4*>(cb + (size_t)bidx * DDIM);
        float* oq = out_q + (size_t)r * DDIM;   // only 4B-aligned: scalar stores
        #pragma unroll
        for (int i = 0; i < DDIM / 4; i++) {
            float4 cv = crow[i];
            float x0 = as_float2(xd[4 * i + 0]).x;
            float x1 = as_float2(xd[4 * i + 1]).x;
            float x2 = as_float2(xd[4 * i + 2]).x;
            float x3 = as_float2(xd[4 * i + 3]).x;
            float o0 = x0 + (cv.x - x0);
            float o1 = x1 + (cv.y - x1);
            float o2 = x2 + (cv.z - x2);
            float o3 = x3 + (cv.w - x3);
            float t0 = o0 - x0; lsum = fmaf(t0, t0, lsum);
            float t1 = o1 - x1; lsum = fmaf(t1, t1, lsum);
            float t2 = o2 - x2; lsum = fmaf(t2, t2, lsum);
            float t3 = o3 - x3; lsum = fmaf(t3, t3, lsum);
            oq[4 * i + 0] = o0;
            oq[4 * i + 1] = o1;
            oq[4 * i + 2] = o2;
            oq[4 * i + 3] = o3;
        }
    }

    // Block loss reduction -> one double atomic per block.
    __shared__ float warp_sums[TPB / 32];
    #pragma unroll
    for (int off = 16; off; off >>= 1)
        lsum += __shfl_down_sync(0xffffffffu, lsum, off);
    if ((tid & 31) == 0) warp_sums[tid >> 5] = lsum;
    __syncthreads();
    if (tid == 0) {
        float b = 0.f;
        #pragma unroll
        for (int w = 0; w < TPB / 32; w++) b += warp_sums[w];
        atomicAdd(&g_loss_sum, (double)b);
    }
}

extern "C" void kernel_launch(void* const* d_in, const int* in_sizes, int n_in,
                              void* d_out, int out_size)
{
    const float* x  = (const float*)d_in[0];   // inputs  [128,32,32,64]
    const float* cb = (const float*)d_in[1];   // codebook [512,64]
    const int n_elem = in_sizes[0];            // 8388608
    const int nrows  = n_elem / DDIM;          // 131072

    float* out      = (float*)d_out;
    float* out_loss = out;
    float* out_q    = out + 1;
    float* out_idx  = out + 1 + (size_t)nrows * DDIM;

    const int smem_bytes = (KCODES * DDIM + KCODES) * (int)sizeof(float);
    cudaFuncSetAttribute(vq_main_kernel,
                         cudaFuncAttributeMaxDynamicSharedMemorySize, smem_bytes);

    int sms = 148;
    cudaDeviceGetAttribute(&sms, cudaDevAttrMultiProcessorCount, 0);

    vq_zero_kernel<<<1, 1>>>();
    vq_main_kernel<<<sms, TPB, smem_bytes>>>(x, cb, out_q, out_idx, nrows);
    vq_finalize_kernel<<<1, 1>>>(out_loss, n_elem);
}

// round 3
// speedup vs baseline: 1.0315x; 1.0315x over previous
#include <cuda_runtime.h>

// QuantizedCodebook (VQ-VAE): N=131072 rows, D=64, K=512.
// out layout (confirmed R2): [loss(1) | quantize(N*D) | indices(N)] fp32.
// out+1 is only 4B-aligned -> quantize written with 32-bit stores.

#define KCODES 512
#define DDIM   64
#define TPB    256
#define MAXBLK 512

__device__ double   g_partials[MAXBLK];
__device__ unsigned g_done;   // zero-init; last block resets to 0 each run

__device__ __forceinline__ unsigned long long ffma2(unsigned long long a,
                                                    unsigned long long b,
                                                    unsigned long long c) {
    unsigned long long d;
    asm("fma.rn.f32x2 %0, %1, %2, %3;" : "=l"(d) : "l"(a), "l"(b), "l"(c));
    return d;
}
__device__ __forceinline__ float2 as_float2(unsigned long long a) {
    float2 f;
    asm("mov.b64 {%0, %1}, %2;" : "=f"(f.x), "=f"(f.y) : "l"(a));
    return f;
}

__global__ void __launch_bounds__(TPB, 1)
vq_kernel(const float* __restrict__ x, const float* __restrict__ cb,
          float* __restrict__ out, int nrows)
{
    extern __shared__ float smem[];
    float* scb = smem;                 // KCODES*DDIM floats, plain [K][D]
    float* scq = smem + KCODES * DDIM; // KCODES floats: ||c_j||^2

    float* out_q   = out + 1;
    float* out_idx = out + 1 + (size_t)nrows * DDIM;

    const int tid = threadIdx.x;

    // Codebook -> smem (plain layout), plus ||c||^2.
    for (int idx = tid; idx < KCODES * DDIM; idx += TPB)
        scb[idx] = cb[idx];
    __syncthreads();
    for (int j = tid; j < KCODES; j += TPB) {
        const float* c = scb + j * DDIM;
        float s = 0.f;
        #pragma unroll
        for (int i = 0; i < DDIM; i++) s = fmaf(c[i], c[i], s);
        scq[j] = s;
    }
    __syncthreads();

    // Persistent: block owns contiguous row range.
    const int nb    = gridDim.x;
    const int start = (int)(((long long)blockIdx.x * nrows) / nb);
    const int end   = (int)(((long long)(blockIdx.x + 1) * nrows) / nb);

    float lsum = 0.f;

    for (int r = start + tid; r < end; r += TPB) {
        // Row as 32 packed f32x2 (natural {x_i, x_{i+1}} pairs): 64 regs.
        const ulonglong2* xr =
            reinterpret_cast<const ulonglong2*>(x + (size_t)r * DDIM);
        unsigned long long x2[DDIM / 2];
        #pragma unroll
        for (int i = 0; i < DDIM / 4; i++) {
            ulonglong2 v = xr[i];
            x2[2 * i + 0] = v.x;
            x2[2 * i + 1] = v.y;
        }

        float best = 3.402823466e38f;
        int   bidx = 0;

        // 4 codes per outer iter: 4 independent f32x2 accumulator chains.
        #pragma unroll 1
        for (int j = 0; j < KCODES; j += 4) {
            const ulonglong2* c0 =
                reinterpret_cast<const ulonglong2*>(scb + (j + 0) * DDIM);
            const ulonglong2* c1 =
                reinterpret_cast<const ulonglong2*>(scb + (j + 1) * DDIM);
            const ulonglong2* c2 =
                reinterpret_cast<const ulonglong2*>(scb + (j + 2) * DDIM);
            const ulonglong2* c3 =
                reinterpret_cast<const ulonglong2*>(scb + (j + 3) * DDIM);
            unsigned long long a0 = 0ull, a1 = 0ull, a2 = 0ull, a3 = 0ull;
            #pragma unroll
            for (int i = 0; i < DDIM / 4; i++) {
                ulonglong2 q0 = c0[i];
                a0 = ffma2(x2[2 * i],     q0.x, a0);
                a0 = ffma2(x2[2 * i + 1], q0.y, a0);
                ulonglong2 q1 = c1[i];
                a1 = ffma2(x2[2 * i],     q1.x, a1);
                a1 = ffma2(x2[2 * i + 1], q1.y, a1);
                ulonglong2 q2 = c2[i];
                a2 = ffma2(x2[2 * i],     q2.x, a2);
                a2 = ffma2(x2[2 * i + 1], q2.y, a2);
                ulonglong2 q3 = c3[i];
                a3 = ffma2(x2[2 * i],     q3.x, a3);
                a3 = ffma2(x2[2 * i + 1], q3.y, a3);
            }
            float2 f0 = as_float2(a0);
            float2 f1 = as_float2(a1);
            float2 f2 = as_float2(a2);
            float2 f3 = as_float2(a3);
            float s0 = fmaf(-2.f, f0.x + f0.y, scq[j + 0]);
            float s1 = fmaf(-2.f, f1.x + f1.y, scq[j + 1]);
            float s2 = fmaf(-2.f, f2.x + f2.y, scq[j + 2]);
            float s3 = fmaf(-2.f, f3.x + f3.y, scq[j + 3]);
            // strict < in ascending order == jnp.argmin first-min
            if (s0 < best) { best = s0; bidx = j + 0; }
            if (s1 < best) { best = s1; bidx = j + 1; }
            if (s2 < best) { best = s2; bidx = j + 2; }
            if (s3 < best) { best = s3; bidx = j + 3; }
        }

        // Epilogue: index, quantize = x + (c - x), loss accum.
        out_idx[r] = (float)bidx;
        const float4* crow =
            reinterpret_cast<const float4*>(cb + (size_t)bidx * DDIM);
        float* oq = out_q + (size_t)r * DDIM;   // 4B-aligned only
        #pragma unroll
        for (int i = 0; i < DDIM / 4; i++) {
            float4 cv = crow[i];
            float2 xa = as_float2(x2[2 * i + 0]);
            float2 xb = as_float2(x2[2 * i + 1]);
            float o0 = xa.x + (cv.x - xa.x);
            float o1 = xa.y + (cv.y - xa.y);
            float o2 = xb.x + (cv.z - xb.x);
            float o3 = xb.y + (cv.w - xb.y);
            float t0 = o0 - xa.x; lsum = fmaf(t0, t0, lsum);
            float t1 = o1 - xa.y; lsum = fmaf(t1, t1, lsum);
            float t2 = o2 - xb.x; lsum = fmaf(t2, t2, lsum);
            float t3 = o3 - xb.y; lsum = fmaf(t3, t3, lsum);
            oq[4 * i + 0] = o0;
            oq[4 * i + 1] = o1;
            oq[4 * i + 2] = o2;
            oq[4 * i + 3] = o3;
        }
    }

    // Block reduction -> double partial; last block finalizes loss.
    __shared__ float warp_sums[TPB / 32];
    #pragma unroll
    for (int off = 16; off; off >>= 1)
        lsum += __shfl_down_sync(0xffffffffu, lsum, off);
    if ((tid & 31) == 0) warp_sums[tid >> 5] = lsum;
    __syncthreads();
    if (tid == 0) {
        float b = 0.f;
        #pragma unroll
        for (int w = 0; w < TPB / 32; w++) b += warp_sums[w];
        g_partials[blockIdx.x] = (double)b;
        __threadfence();
        unsigned done = atomicAdd(&g_done, 1u);
        if (done == gridDim.x - 1) {
            double total = 0.0;
            for (int k = 0; k < gridDim.x; k++) total += g_partials[k];
            out[0] = (float)(total * 1.25 / ((double)nrows * DDIM));
            __threadfence();
            g_done = 0;   // self-reset for next graph replay
        }
    }
}

extern "C" void kernel_launch(void* const* d_in, const int* in_sizes, int n_in,
                              void* d_out, int out_size)
{
    const float* x  = (const float*)d_in[0];   // inputs  [128,32,32,64]
    const float* cb = (const float*)d_in[1];   // codebook [512,64]
    const int n_elem = in_sizes[0];            // 8388608
    const int nrows  = n_elem / DDIM;          // 131072

    const int smem_bytes = (KCODES * DDIM + KCODES) * (int)sizeof(float);
    cudaFuncSetAttribute(vq_kernel,
                         cudaFuncAttributeMaxDynamicSharedMemorySize, smem_bytes);

    int sms = 148;
    cudaDeviceGetAttribute(&sms, cudaDevAttrMultiProcessorCount, 0);
    if (sms > MAXBLK) sms = MAXBLK;

    vq_kernel<<<sms, TPB, smem_bytes>>>(x, cb, (float*)d_out, nrows);
}